// round 5
// baseline (speedup 1.0000x reference)
#include <cuda_runtime.h>
#include <math.h>

#define BLOCK 64
#define NSH 81            // sum(2l+1), l=0..8
#define PERSIST_GRID 1628 // 148 SMs x 11 CTAs/SM (smem-capped occupancy)

// Real spherical harmonics (e3nn SphericalHarmonicsAlphaBeta, l=0..8, mul=1).
// out[n, l*l + l + m] = P̄_{l,|m|}(cos b) * sin(b)^|m| * A_m(a)
//   A_m = 1 (m=0), sqrt(2)*cos(m a) (m>0), sqrt(2)*sin(|m| a) (m<0)
// P̄ via stable fully-normalized ALF recurrences (no Condon-Shortley phase).
// PERSISTENT version: one wave of CTAs, grid-stride loop over 64-point tiles.
// Each warp owns a private 32x81 smem tile (__syncwarp only, no CTA barrier).
__global__ __launch_bounds__(BLOCK)
void sh_ab_kernel(const float* __restrict__ alpha,
                  const float* __restrict__ beta,
                  float* __restrict__ out, int n, int ntiles)
{
    __shared__ __align__(16) float sh[BLOCK * NSH];   // 20736 B -> 11 CTAs/SM

    const int tid  = threadIdx.x;
    const int wid  = tid >> 5;
    const int lane = tid & 31;
    const float SQ2 = 1.41421356237309515f;

    float* warp_tile = &sh[wid * 32 * NSH];
    float* row = &warp_tile[lane * NSH];

    int t = blockIdx.x;
    // preload first tile's inputs
    float a = 0.f, b = 0.f;
    {
        const int p = t * BLOCK + wid * 32 + lane;
        if (t < ntiles && p < n) { a = alpha[p]; b = beta[p]; }
    }

    while (t < ntiles) {
        const int t_next = t + gridDim.x;

        float sa, ca, sb, cb;
        __sincosf(a, &sa, &ca);
        __sincosf(b, &sb, &cb);
        const float z = cb;
        const float y = sb;

        // cos(m a), sin(m a) for m=0..8 via Chebyshev recurrence
        float cm[9], sn[9];
        cm[0] = 1.f; sn[0] = 0.f;
        cm[1] = ca;  sn[1] = sa;
        const float t2 = 2.f * ca;
#pragma unroll
        for (int m = 2; m <= 8; ++m) {
            cm[m] = t2 * cm[m-1] - cm[m-2];
            sn[m] = t2 * sn[m-1] - sn[m-2];
        }

        // m-major sweep of P̄_{l,m}; write products into this thread's row
        float pmm = 0.28209479177387814f;   // P̄_00 = sqrt(1/4pi)
#pragma unroll
        for (int m = 0; m <= 8; ++m) {
            if (m > 0)
                pmm *= sqrtf((2.f*m + 1.f) / (2.f*m)) * y;

            const float Ac = (m == 0) ? 1.f : SQ2 * cm[m];
            const float As = SQ2 * sn[m];

            float plm2 = pmm;
            {
                const int l = m;
                row[l*l + l + m] = plm2 * Ac;
                if (m > 0) row[l*l + l - m] = plm2 * As;
            }
            if (m < 8) {
                float plm1 = sqrtf(2.f*m + 3.f) * z * pmm;
                {
                    const int l = m + 1;
                    row[l*l + l + m] = plm1 * Ac;
                    if (m > 0) row[l*l + l - m] = plm1 * As;
                }
#pragma unroll
                for (int l = m + 2; l <= 8; ++l) {
                    const float al = sqrtf((4.f*l*l - 1.f) / (float)(l*l - m*m));
                    const float bl = sqrtf((float)((l-1)*(l-1) - m*m) /
                                           (4.f*(l-1)*(l-1) - 1.f));
                    const float pl = al * (z * plm1 - bl * plm2);
                    row[l*l + l + m] = pl * Ac;
                    if (m > 0) row[l*l + l - m] = pl * As;
                    plm2 = plm1; plm1 = pl;
                }
            }
        }

        // prefetch next tile's inputs while the store phase runs
        float a2 = 0.f, b2 = 0.f;
        if (t_next < ntiles) {
            const int p = t_next * BLOCK + wid * 32 + lane;
            if (p < n) { a2 = alpha[p]; b2 = beta[p]; }
        }

        __syncwarp();

        // Warp-local coalesced streaming writeback: 32*81 floats = 648 float4
        const long long warp_base = (long long)(t * BLOCK + wid * 32) * NSH;
        const int remaining = n - (t * BLOCK + wid * 32);
        if (remaining >= 32) {
            float4* dst = reinterpret_cast<float4*>(out + warp_base);
            const float4* src = reinterpret_cast<const float4*>(warp_tile);
#pragma unroll 5
            for (int i = lane; i < (32 * NSH) / 4; i += 32)
                __stcs(&dst[i], src[i]);
        } else {
            const int floats = (remaining > 0 ? remaining : 0) * NSH;
            for (int i = lane; i < floats; i += 32)
                __stcs(&out[warp_base + i], warp_tile[i]);
        }

        __syncwarp();   // smem tile is reused next iteration
        a = a2; b = b2;
        t = t_next;
    }
}

extern "C" void kernel_launch(void* const* d_in, const int* in_sizes, int n_in,
                              void* d_out, int out_size)
{
    const float* alpha = (const float*)d_in[0];
    const float* beta  = (const float*)d_in[1];
    float* out = (float*)d_out;
    const int n = in_sizes[0];
    const int ntiles = (n + BLOCK - 1) / BLOCK;
    const int grid = ntiles < PERSIST_GRID ? ntiles : PERSIST_GRID;
    sh_ab_kernel<<<grid, BLOCK>>>(alpha, beta, out, n, ntiles);
}

// round 6
// speedup vs baseline: 1.0277x; 1.0277x over previous
#include <cuda_runtime.h>
#include <math.h>

#define BLOCK 64
#define NSH 81   // sum(2l+1), l=0..8

// Real spherical harmonics (e3nn SphericalHarmonicsAlphaBeta, l=0..8, mul=1).
// out[n, l*l + l + m] = P̄_{l,|m|}(cos b) * sin(b)^|m| * A_m(a)
//   A_m = 1 (m=0), sqrt(2)*cos(m a) (m>0), sqrt(2)*sin(|m| a) (m<0)
// P̄ via stable fully-normalized ALF recurrences (no Condon-Shortley phase).
// Writeback: warp-local smem tile, streamed out with 256-bit stores
// (st.global.cs.v8.f32, sm_100+) to halve store-issue wavefronts.
__global__ __launch_bounds__(BLOCK)
void sh_ab_kernel(const float* __restrict__ alpha,
                  const float* __restrict__ beta,
                  float* __restrict__ out, int n)
{
    __shared__ __align__(32) float sh[BLOCK * NSH];   // 20736 B -> 11 CTAs/SM

    const int tid  = threadIdx.x;
    const int wid  = tid >> 5;          // warp in block
    const int lane = tid & 31;
    const int point = blockIdx.x * BLOCK + tid;

    float a = 0.f, b = 0.f;
    if (point < n) { a = alpha[point]; b = beta[point]; }

    float sa, ca, sb, cb;
    __sincosf(a, &sa, &ca);
    __sincosf(b, &sb, &cb);
    const float z = cb;   // polynomial variable
    const float y = sb;   // sin(beta) >= 0 on [0, pi]

    // cos(m a), sin(m a) for m=0..8 via Chebyshev recurrence
    float cm[9], sn[9];
    cm[0] = 1.f; sn[0] = 0.f;
    cm[1] = ca;  sn[1] = sa;
    const float t2 = 2.f * ca;
#pragma unroll
    for (int m = 2; m <= 8; ++m) {
        cm[m] = t2 * cm[m-1] - cm[m-2];
        sn[m] = t2 * sn[m-1] - sn[m-2];
    }

    const float SQ2 = 1.41421356237309515f;
    float* warp_tile = &sh[wid * 32 * NSH];
    float* row = &warp_tile[lane * NSH];

    // m-major sweep: tiny live register set per column
    float pmm = 0.28209479177387814f;   // P̄_00 = sqrt(1/4pi)
#pragma unroll
    for (int m = 0; m <= 8; ++m) {
        if (m > 0)
            pmm *= sqrtf((2.f*m + 1.f) / (2.f*m)) * y;   // sectoral step

        const float Ac = (m == 0) ? 1.f : SQ2 * cm[m];
        const float As = SQ2 * sn[m];

        // l = m
        float plm2 = pmm;
        {
            const int l = m;
            row[l*l + l + m] = plm2 * Ac;
            if (m > 0) row[l*l + l - m] = plm2 * As;
        }
        if (m < 8) {
            // l = m+1
            float plm1 = sqrtf(2.f*m + 3.f) * z * pmm;
            {
                const int l = m + 1;
                row[l*l + l + m] = plm1 * Ac;
                if (m > 0) row[l*l + l - m] = plm1 * As;
            }
            // l = m+2 .. 8
#pragma unroll
            for (int l = m + 2; l <= 8; ++l) {
                const float al = sqrtf((4.f*l*l - 1.f) / (float)(l*l - m*m));
                const float bl = sqrtf((float)((l-1)*(l-1) - m*m) /
                                       (4.f*(l-1)*(l-1) - 1.f));
                const float pl = al * (z * plm1 - bl * plm2);
                row[l*l + l + m] = pl * Ac;
                if (m > 0) row[l*l + l - m] = pl * As;
                plm2 = plm1; plm1 = pl;
            }
        }
    }

    __syncwarp();

    // Warp-local coalesced writeback: 32*81 floats = 324 x 32B vectors
    const long long warp_base =
        (long long)(blockIdx.x * BLOCK + wid * 32) * NSH;
    const int remaining = n - (blockIdx.x * BLOCK + wid * 32);
    if (remaining >= 32) {
        float* dst = out + warp_base;
        const float4* src4 = reinterpret_cast<const float4*>(warp_tile);
        // 320 full float8 vectors: 10 per lane
#pragma unroll
        for (int k = 0; k < 10; ++k) {
            const int i = k * 32 + lane;        // float8 index
            const float4 lo = src4[2*i];
            const float4 hi = src4[2*i + 1];
            asm volatile(
                "st.global.cs.v8.f32 [%0], {%1,%2,%3,%4,%5,%6,%7,%8};"
                :: "l"(dst + 8LL*i),
                   "f"(lo.x), "f"(lo.y), "f"(lo.z), "f"(lo.w),
                   "f"(hi.x), "f"(hi.y), "f"(hi.z), "f"(hi.w)
                : "memory");
        }
        // remainder: float8 indices 320..323 -> float4 indices 640..647
        if (lane < 8) {
            const int i4 = 640 + lane;
            __stcs(reinterpret_cast<float4*>(dst) + i4, src4[i4]);
        }
    } else {
        const int floats = (remaining > 0 ? remaining : 0) * NSH;
        for (int i = lane; i < floats; i += 32)
            __stcs(&out[warp_base + i], warp_tile[i]);
    }
}

extern "C" void kernel_launch(void* const* d_in, const int* in_sizes, int n_in,
                              void* d_out, int out_size)
{
    const float* alpha = (const float*)d_in[0];
    const float* beta  = (const float*)d_in[1];
    float* out = (float*)d_out;
    const int n = in_sizes[0];
    const int grid = (n + BLOCK - 1) / BLOCK;
    sh_ab_kernel<<<grid, BLOCK>>>(alpha, beta, out, n);
}

// round 7
// speedup vs baseline: 1.1973x; 1.1651x over previous
#include <cuda_runtime.h>
#include <math.h>

#define BLOCK 32
#define NSH 81   // sum(2l+1), l=0..8

// Real spherical harmonics (e3nn SphericalHarmonicsAlphaBeta, l=0..8, mul=1).
// out[n, l*l + l + m] = P̄_{l,|m|}(cos b) * sin(b)^|m| * A_m(a)
//   A_m = 1 (m=0), sqrt(2)*cos(m a) (m>0), sqrt(2)*sin(|m| a) (m<0)
// P̄ via stable fully-normalized ALF recurrences (no Condon-Shortley phase).
// One warp per CTA: 32-point tile staged in 10.1 KB smem (stride-81 rows,
// 81 odd -> conflict-free), flushed as coalesced float4 streaming stores.
// 22 independent single-warp CTAs per SM for maximum scheduling decoupling.
__global__ __launch_bounds__(BLOCK)
void sh_ab_kernel(const float* __restrict__ alpha,
                  const float* __restrict__ beta,
                  float* __restrict__ out, int n)
{
    __shared__ __align__(16) float tile[BLOCK * NSH];   // 10368 B

    const int lane = threadIdx.x;
    const int point = blockIdx.x * BLOCK + lane;

    float a = 0.f, b = 0.f;
    if (point < n) { a = alpha[point]; b = beta[point]; }

    float sa, ca, sb, cb;
    __sincosf(a, &sa, &ca);
    __sincosf(b, &sb, &cb);
    const float z = cb;   // polynomial variable
    const float y = sb;   // sin(beta) >= 0 on [0, pi]

    // cos(m a), sin(m a) for m=0..8 via Chebyshev recurrence
    float cm[9], sn[9];
    cm[0] = 1.f; sn[0] = 0.f;
    cm[1] = ca;  sn[1] = sa;
    const float t2 = 2.f * ca;
#pragma unroll
    for (int m = 2; m <= 8; ++m) {
        cm[m] = t2 * cm[m-1] - cm[m-2];
        sn[m] = t2 * sn[m-1] - sn[m-2];
    }

    const float SQ2 = 1.41421356237309515f;
    float* row = &tile[lane * NSH];

    // m-major sweep: tiny live register set per column
    float pmm = 0.28209479177387814f;   // P̄_00 = sqrt(1/4pi)
#pragma unroll
    for (int m = 0; m <= 8; ++m) {
        if (m > 0)
            pmm *= sqrtf((2.f*m + 1.f) / (2.f*m)) * y;   // sectoral step

        const float Ac = (m == 0) ? 1.f : SQ2 * cm[m];
        const float As = SQ2 * sn[m];

        // l = m
        float plm2 = pmm;
        {
            const int l = m;
            row[l*l + l + m] = plm2 * Ac;
            if (m > 0) row[l*l + l - m] = plm2 * As;
        }
        if (m < 8) {
            // l = m+1
            float plm1 = sqrtf(2.f*m + 3.f) * z * pmm;
            {
                const int l = m + 1;
                row[l*l + l + m] = plm1 * Ac;
                if (m > 0) row[l*l + l - m] = plm1 * As;
            }
            // l = m+2 .. 8
#pragma unroll
            for (int l = m + 2; l <= 8; ++l) {
                const float al = sqrtf((4.f*l*l - 1.f) / (float)(l*l - m*m));
                const float bl = sqrtf((float)((l-1)*(l-1) - m*m) /
                                       (4.f*(l-1)*(l-1) - 1.f));
                const float pl = al * (z * plm1 - bl * plm2);
                row[l*l + l + m] = pl * Ac;
                if (m > 0) row[l*l + l - m] = pl * As;
                plm2 = plm1; plm1 = pl;
            }
        }
    }

    __syncwarp();

    // Coalesced streaming writeback: 32*81 floats = 648 float4
    const long long base = (long long)blockIdx.x * (BLOCK * NSH);
    const int remaining = n - blockIdx.x * BLOCK;
    if (remaining >= BLOCK) {
        float4* dst = reinterpret_cast<float4*>(out + base);
        const float4* src = reinterpret_cast<const float4*>(tile);
#pragma unroll 5
        for (int i = lane; i < (BLOCK * NSH) / 4; i += BLOCK)
            __stcs(&dst[i], src[i]);
    } else {
        const int floats = (remaining > 0 ? remaining : 0) * NSH;
        for (int i = lane; i < floats; i += BLOCK)
            __stcs(&out[base + i], tile[i]);
    }
}

extern "C" void kernel_launch(void* const* d_in, const int* in_sizes, int n_in,
                              void* d_out, int out_size)
{
    const float* alpha = (const float*)d_in[0];
    const float* beta  = (const float*)d_in[1];
    float* out = (float*)d_out;
    const int n = in_sizes[0];
    const int grid = (n + BLOCK - 1) / BLOCK;
    sh_ab_kernel<<<grid, BLOCK>>>(alpha, beta, out, n);
}